// round 4
// baseline (speedup 1.0000x reference)
#include <cuda_runtime.h>
#include <cuda_bf16.h>

// velocity = MLP(concat(zone_embedding, person_attrs, time_vec)).
// GCN layers are dead code w.r.t. the output; person/time layer-1
// contributions are row-constant, folded into g_c1 by setup_kernel.
//
// R4: weight reads moved from smem to warp-uniform GLOBAL loads. R2/R3 showed
// the LDS data path does not dedup broadcasts (wavefronts = lane-bytes/128),
// so identical-address LDS.128 cost 4 wavefronts; the gmem coalescer dedups
// identical addresses to 1 sector. Weights stay L1-resident (20KB << 228KB).
// No smem staging, no __syncthreads.

#define HID 32
#define H1  64

typedef unsigned long long u64;

__device__ __align__(16) float g_c1[H1];

__device__ __forceinline__ u64 fma2(u64 a, u64 b, u64 c) {
    u64 d;
    asm("fma.rn.f32x2 %0, %1, %2, %3;" : "=l"(d) : "l"(a), "l"(b), "l"(c));
    return d;
}
__device__ __forceinline__ u64 dup2(float x) {
    u64 d;
    asm("mov.b64 %0, {%1, %1};" : "=l"(d) : "f"(x));
    return d;
}
__device__ __forceinline__ float2 unpk2(u64 v) {
    float2 r;
    asm("mov.b64 {%0, %1}, %2;" : "=f"(r.x), "=f"(r.y) : "l"(v));
    return r;
}

// ---------------------------------------------------------------------------
__global__ void setup_kernel(const float* __restrict__ t,
                             const float* __restrict__ pa,
                             const float* __restrict__ Wt1, const float* __restrict__ bt1,
                             const float* __restrict__ Wt2, const float* __restrict__ bt2,
                             const float* __restrict__ Wd1, const float* __restrict__ bd1)
{
    __shared__ float u[16];
    __shared__ float tv[16];
    const int j = threadIdx.x;

    if (j < 16) u[j] = fmaxf(fmaf(t[0], Wt1[j], bt1[j]), 0.0f);
    __syncthreads();

    if (j < 16) {
        float a = bt2[j];
        #pragma unroll
        for (int i = 0; i < 16; i++) a = fmaf(u[i], Wt2[i * 16 + j], a);
        tv[j] = a;
    }
    __syncthreads();

    if (j < H1) {
        float a = bd1[j];
        #pragma unroll
        for (int p = 0; p < 8; p++)  a = fmaf(pa[p], Wd1[(HID + p) * H1 + j], a);
        #pragma unroll
        for (int i = 0; i < 16; i++) a = fmaf(tv[i], Wd1[(HID + 8 + i) * H1 + j], a);
        g_c1[j] = a;
    }
}

// ---------------------------------------------------------------------------
// One thread per row. Weights read directly from global with warp-uniform
// 16B loads (coalesce to 1 sector each, L1-resident). Native row-major
// layouts are j-contiguous, so f32x2 pairs need no transpose.
// ---------------------------------------------------------------------------
__global__ __launch_bounds__(128, 5)
void mlp_kernel(const float* __restrict__ emb,
                const float* __restrict__ Wd1,
                const float* __restrict__ Wd2, const float* __restrict__ bd2,
                const float* __restrict__ Wd3, const float* __restrict__ bd3,
                float* __restrict__ out, int nrows)
{
    const int row = blockIdx.x * 128 + threadIdx.x;
    if (row >= nrows) return;

    const ulonglong2* __restrict__ W1 = reinterpret_cast<const ulonglong2*>(Wd1);  // [k][j2] pairs: (k*32+c*8+q)/2
    const ulonglong2* __restrict__ W2 = reinterpret_cast<const ulonglong2*>(Wd2);
    const ulonglong2* __restrict__ W3 = reinterpret_cast<const ulonglong2*>(Wd3);
    const ulonglong2* __restrict__ C1 = reinterpret_cast<const ulonglong2*>(g_c1);
    const ulonglong2* __restrict__ B2 = reinterpret_cast<const ulonglong2*>(bd2);
    const ulonglong2* __restrict__ B3 = reinterpret_cast<const ulonglong2*>(bd3);

    // Embedding row (lane-scattered float4 loads).
    float z[HID];
    {
        const float4* zp = reinterpret_cast<const float4*>(emb + (size_t)row * HID);
        #pragma unroll
        for (int q = 0; q < 8; q++) {
            float4 v = zp[q];
            z[4*q+0] = v.x; z[4*q+1] = v.y; z[4*q+2] = v.z; z[4*q+3] = v.w;
        }
    }

    // Layer-2 accumulators (32 floats as 16 pairs), init with bias.
    u64 acc2[16];
    #pragma unroll
    for (int q = 0; q < 8; q++) {
        ulonglong2 v = B2[q];
        acc2[2*q] = v.x; acc2[2*q+1] = v.y;
    }

    // Fused layer1 (chunks of 16 outputs) -> relu -> layer2 accumulate.
    #pragma unroll
    for (int c = 0; c < 4; c++) {
        u64 acc1[8];
        #pragma unroll
        for (int q = 0; q < 4; q++) {
            ulonglong2 v = C1[c * 4 + q];
            acc1[2*q] = v.x; acc1[2*q+1] = v.y;
        }

        #pragma unroll
        for (int k = 0; k < 32; k++) {
            u64 zz = dup2(z[k]);
            // Wd1 row k, output pairs [c*8 .. c*8+7]: u64 index k*32 + c*8
            const ulonglong2* w = W1 + (k * 32 + c * 8) / 2;
            #pragma unroll
            for (int q = 0; q < 4; q++) {
                ulonglong2 ww = w[q];
                acc1[2*q]   = fma2(ww.x, zz, acc1[2*q]);
                acc1[2*q+1] = fma2(ww.y, zz, acc1[2*q+1]);
            }
        }

        #pragma unroll
        for (int p = 0; p < 8; p++) {
            float2 h = unpk2(acc1[p]);
            const int k0 = c * 16 + 2 * p;
            u64 hh0 = dup2(fmaxf(h.x, 0.0f));
            u64 hh1 = dup2(fmaxf(h.y, 0.0f));
            const ulonglong2* w0 = W2 + (k0 + 0) * 8;   // 16 u64 per k-row = 8 u64x2
            const ulonglong2* w1 = W2 + (k0 + 1) * 8;
            #pragma unroll
            for (int q = 0; q < 8; q++) {
                ulonglong2 a0 = w0[q];
                ulonglong2 a1 = w1[q];
                u64 t0 = fma2(a0.x, hh0, acc2[2*q]);
                u64 t1 = fma2(a0.y, hh0, acc2[2*q+1]);
                acc2[2*q]   = fma2(a1.x, hh1, t0);
                acc2[2*q+1] = fma2(a1.y, hh1, t1);
            }
        }
    }

    // Layer 3: relu(acc2) -> 32 outs, linear.
    u64 acc3[16];
    #pragma unroll
    for (int q = 0; q < 8; q++) {
        ulonglong2 v = B3[q];
        acc3[2*q] = v.x; acc3[2*q+1] = v.y;
    }

    #pragma unroll
    for (int q = 0; q < 16; q++) {
        float2 h = unpk2(acc2[q]);
        const int k0 = 2 * q;
        u64 hh0 = dup2(fmaxf(h.x, 0.0f));
        u64 hh1 = dup2(fmaxf(h.y, 0.0f));
        const ulonglong2* w0 = W3 + (k0 + 0) * 8;
        const ulonglong2* w1 = W3 + (k0 + 1) * 8;
        #pragma unroll
        for (int p = 0; p < 8; p++) {
            ulonglong2 a0 = w0[p];
            ulonglong2 a1 = w1[p];
            u64 t0 = fma2(a0.x, hh0, acc3[2*p]);
            u64 t1 = fma2(a0.y, hh0, acc3[2*p+1]);
            acc3[2*p]   = fma2(a1.x, hh1, t0);
            acc3[2*p+1] = fma2(a1.y, hh1, t1);
        }
    }

    // Store 32 floats = 8 x 128-bit.
    ulonglong2* op = reinterpret_cast<ulonglong2*>(out + (size_t)row * HID);
    #pragma unroll
    for (int p = 0; p < 8; p++) {
        ulonglong2 v;
        v.x = acc3[2 * p];
        v.y = acc3[2 * p + 1];
        op[p] = v;
    }
}

extern "C" void kernel_launch(void* const* d_in, const int* in_sizes, int n_in,
                              void* d_out, int out_size)
{
    const float* t   = (const float*)d_in[0];
    const float* emb = (const float*)d_in[1];
    const float* pa  = (const float*)d_in[3];
    const float* Wt1 = (const float*)d_in[9];
    const float* bt1 = (const float*)d_in[10];
    const float* Wt2 = (const float*)d_in[11];
    const float* bt2 = (const float*)d_in[12];
    const float* Wd1 = (const float*)d_in[13];
    const float* bd1 = (const float*)d_in[14];
    const float* Wd2 = (const float*)d_in[15];
    const float* bd2 = (const float*)d_in[16];
    const float* Wd3 = (const float*)d_in[17];
    const float* bd3 = (const float*)d_in[18];
    float* out = (float*)d_out;

    const int nrows = in_sizes[1] / HID;

    setup_kernel<<<1, 64>>>(t, pa, Wt1, bt1, Wt2, bt2, Wd1, bd1);
    mlp_kernel<<<(nrows + 127) / 128, 128>>>(emb, Wd1, Wd2, bd2, Wd3, bd3, out, nrows);
}

// round 5
// speedup vs baseline: 2.3894x; 2.3894x over previous
#include <cuda_runtime.h>
#include <cuda_bf16.h>

// velocity = MLP(concat(zone_embedding, person_attrs, time_vec)).
// GCN layers are dead code w.r.t. the output; person/time layer-1
// contributions are row-constant, folded into g_c1 by setup_kernel.
//
// R5: register-block 4 rows per thread. The L1TEX data path charges per-lane
// bytes for broadcast reads (R3: LDS no dedup; R4: uniform LDG 2x worse), so
// per-thread weight traffic is the wall — amortize it over 4 rows. z staged
// transposed in smem; W1+W2 in smem (48KB total, 4 blocks/SM); acc2 in regs;
// W3/biases via tiny uniform LDG. One barrier.

#define HID 32
#define H1  64
#define TPB 64
#define RPB 256

typedef unsigned long long u64;

__device__ __align__(16) float g_c1[H1];

__device__ __forceinline__ u64 fma2(u64 a, u64 b, u64 c) {
    u64 d;
    asm("fma.rn.f32x2 %0, %1, %2, %3;" : "=l"(d) : "l"(a), "l"(b), "l"(c));
    return d;
}
__device__ __forceinline__ u64 dup2(float x) {
    u64 d;
    asm("mov.b64 %0, {%1, %1};" : "=l"(d) : "f"(x));
    return d;
}
__device__ __forceinline__ float2 unpk2(u64 v) {
    float2 r;
    asm("mov.b64 {%0, %1}, %2;" : "=f"(r.x), "=f"(r.y) : "l"(v));
    return r;
}

// ---------------------------------------------------------------------------
__global__ void setup_kernel(const float* __restrict__ t,
                             const float* __restrict__ pa,
                             const float* __restrict__ Wt1, const float* __restrict__ bt1,
                             const float* __restrict__ Wt2, const float* __restrict__ bt2,
                             const float* __restrict__ Wd1, const float* __restrict__ bd1)
{
    __shared__ float u[16];
    __shared__ float tv[16];
    const int j = threadIdx.x;

    if (j < 16) u[j] = fmaxf(fmaf(t[0], Wt1[j], bt1[j]), 0.0f);
    __syncthreads();

    if (j < 16) {
        float a = bt2[j];
        #pragma unroll
        for (int i = 0; i < 16; i++) a = fmaf(u[i], Wt2[i * 16 + j], a);
        tv[j] = a;
    }
    __syncthreads();

    if (j < H1) {
        float a = bd1[j];
        #pragma unroll
        for (int p = 0; p < 8; p++)  a = fmaf(pa[p], Wd1[(HID + p) * H1 + j], a);
        #pragma unroll
        for (int i = 0; i < 16; i++) a = fmaf(tv[i], Wd1[(HID + 8 + i) * H1 + j], a);
        g_c1[j] = a;
    }
}

// ---------------------------------------------------------------------------
// 64 threads/block, 256 rows/block, thread t owns rows 4t..4t+3.
// ---------------------------------------------------------------------------
__global__ void __launch_bounds__(TPB)
mlp_kernel(const float* __restrict__ emb,
           const float* __restrict__ Wd1,
           const float* __restrict__ Wd2, const float* __restrict__ bd2,
           const float* __restrict__ Wd3, const float* __restrict__ bd3,
           float* __restrict__ out, int nrows)
{
    __shared__ __align__(16) float z_s[32][RPB];   // transposed z tile, 32KB
    __shared__ __align__(16) float w_s[4096];      // [0..2047] W1, [2048..4095] W2

    const int tid = threadIdx.x;
    const int rb  = blockIdx.x * RPB;

    // --- P0: stage W1 (zone rows of Wd1) + W2; load z tile transposed ---
    {
        const float4* w1v = reinterpret_cast<const float4*>(Wd1);  // first 512 f4 = rows 0..31
        const float4* w2v = reinterpret_cast<const float4*>(Wd2);
        float4* ws = reinterpret_cast<float4*>(w_s);
        #pragma unroll
        for (int i = tid; i < 512; i += TPB) ws[i] = w1v[i];
        #pragma unroll
        for (int i = tid; i < 512; i += TPB) ws[512 + i] = w2v[i];
    }
    {
        const float4* ev = reinterpret_cast<const float4*>(emb);
        #pragma unroll
        for (int i = tid; i < RPB * 8; i += TPB) {
            int row = i & (RPB - 1);
            int c4  = i >> 8;
            if (rb + row < nrows) {
                float4 v = ev[(size_t)(rb + row) * 8 + c4];
                z_s[4 * c4 + 0][row] = v.x;
                z_s[4 * c4 + 1][row] = v.y;
                z_s[4 * c4 + 2][row] = v.z;
                z_s[4 * c4 + 3][row] = v.w;
            }
        }
    }
    __syncthreads();

    // --- P1: fused layer1 -> relu -> layer2 accumulate (acc2 in regs) ---
    u64 acc2[4][16];
    #pragma unroll
    for (int r = 0; r < 4; r++)
        #pragma unroll
        for (int q = 0; q < 16; q++) acc2[r][q] = 0ull;   // bias b2 added in P3

    for (int c = 0; c < 4; ++c) {                 // rolled chunk loop (16 h1 outs)
        u64 a1[4][8];
        {
            const ulonglong2* c1v = reinterpret_cast<const ulonglong2*>(g_c1 + 16 * c);
            ulonglong2 p0 = c1v[0], p1 = c1v[1], p2 = c1v[2], p3 = c1v[3];
            #pragma unroll
            for (int r = 0; r < 4; r++) {
                a1[r][0] = p0.x; a1[r][1] = p0.y;
                a1[r][2] = p1.x; a1[r][3] = p1.y;
                a1[r][4] = p2.x; a1[r][5] = p2.y;
                a1[r][6] = p3.x; a1[r][7] = p3.y;
            }
        }

        const float* wp = w_s + 16 * c;
        #pragma unroll 2
        for (int k = 0; k < 32; ++k) {
            float4 zz = *reinterpret_cast<const float4*>(&z_s[k][4 * tid]);
            u64 zr0 = dup2(zz.x), zr1 = dup2(zz.y), zr2 = dup2(zz.z), zr3 = dup2(zz.w);
            const ulonglong2* wv = reinterpret_cast<const ulonglong2*>(wp + k * 64);
            ulonglong2 w0 = wv[0], w1 = wv[1], w2 = wv[2], w3 = wv[3];

            #define L1ROW(r, zr) \
                a1[r][0] = fma2(w0.x, zr, a1[r][0]); a1[r][1] = fma2(w0.y, zr, a1[r][1]); \
                a1[r][2] = fma2(w1.x, zr, a1[r][2]); a1[r][3] = fma2(w1.y, zr, a1[r][3]); \
                a1[r][4] = fma2(w2.x, zr, a1[r][4]); a1[r][5] = fma2(w2.y, zr, a1[r][5]); \
                a1[r][6] = fma2(w3.x, zr, a1[r][6]); a1[r][7] = fma2(w3.y, zr, a1[r][7]);
            L1ROW(0, zr0) L1ROW(1, zr1) L1ROW(2, zr2) L1ROW(3, zr3)
            #undef L1ROW
        }

        // relu(h1 pair) -> accumulate into acc2 (h1 indices 16c+2p, 16c+2p+1)
        #pragma unroll
        for (int p = 0; p < 8; ++p) {
            u64 hA[4], hB[4];
            #pragma unroll
            for (int r = 0; r < 4; r++) {
                float2 h = unpk2(a1[r][p]);
                hA[r] = dup2(fmaxf(h.x, 0.0f));
                hB[r] = dup2(fmaxf(h.y, 0.0f));
            }
            const ulonglong2* wra = reinterpret_cast<const ulonglong2*>(w_s + 2048 + (16 * c + 2 * p) * 32);
            const ulonglong2* wrb = reinterpret_cast<const ulonglong2*>(w_s + 2048 + (16 * c + 2 * p + 1) * 32);
            #pragma unroll
            for (int m = 0; m < 8; ++m) {
                ulonglong2 wa = wra[m], wb = wrb[m];
                #pragma unroll
                for (int r = 0; r < 4; r++) {
                    acc2[r][2 * m]     = fma2(wb.x, hB[r], fma2(wa.x, hA[r], acc2[r][2 * m]));
                    acc2[r][2 * m + 1] = fma2(wb.y, hB[r], fma2(wa.y, hA[r], acc2[r][2 * m + 1]));
                }
            }
        }
    }

    // --- P3: h2 = relu(acc2 + b2); layer3; store. W3/b2/b3 via uniform LDG ---
    const u64* b2u = reinterpret_cast<const u64*>(bd2);
    const ulonglong2* b3v = reinterpret_cast<const ulonglong2*>(bd3);

    for (int c3 = 0; c3 < 2; ++c3) {              // rolled: 16 outs per chunk
        u64 a3[4][8];
        {
            ulonglong2 q0 = b3v[c3 * 4 + 0], q1 = b3v[c3 * 4 + 1];
            ulonglong2 q2 = b3v[c3 * 4 + 2], q3 = b3v[c3 * 4 + 3];
            #pragma unroll
            for (int r = 0; r < 4; r++) {
                a3[r][0] = q0.x; a3[r][1] = q0.y;
                a3[r][2] = q1.x; a3[r][3] = q1.y;
                a3[r][4] = q2.x; a3[r][5] = q2.y;
                a3[r][6] = q3.x; a3[r][7] = q3.y;
            }
        }

        #pragma unroll
        for (int q = 0; q < 16; ++q) {            // h2 pair (2q, 2q+1)
            float2 bb = unpk2(b2u[q]);
            u64 hA[4], hB[4];
            #pragma unroll
            for (int r = 0; r < 4; r++) {
                float2 h = unpk2(acc2[r][q]);
                hA[r] = dup2(fmaxf(h.x + bb.x, 0.0f));
                hB[r] = dup2(fmaxf(h.y + bb.y, 0.0f));
            }
            const ulonglong2* wra = reinterpret_cast<const ulonglong2*>(Wd3 + (2 * q)     * 32 + 16 * c3);
            const ulonglong2* wrb = reinterpret_cast<const ulonglong2*>(Wd3 + (2 * q + 1) * 32 + 16 * c3);
            #pragma unroll
            for (int m = 0; m < 4; ++m) {
                ulonglong2 wa = wra[m], wb = wrb[m];
                #pragma unroll
                for (int r = 0; r < 4; r++) {
                    a3[r][2 * m]     = fma2(wb.x, hB[r], fma2(wa.x, hA[r], a3[r][2 * m]));
                    a3[r][2 * m + 1] = fma2(wb.y, hB[r], fma2(wa.y, hA[r], a3[r][2 * m + 1]));
                }
            }
        }

        #pragma unroll
        for (int r = 0; r < 4; r++) {
            int row = rb + 4 * tid + r;
            if (row < nrows) {
                ulonglong2* op = reinterpret_cast<ulonglong2*>(out + (size_t)row * HID + 16 * c3);
                ulonglong2 v0; v0.x = a3[r][0]; v0.y = a3[r][1];
                ulonglong2 v1; v1.x = a3[r][2]; v1.y = a3[r][3];
                ulonglong2 v2; v2.x = a3[r][4]; v2.y = a3[r][5];
                ulonglong2 v3; v3.x = a3[r][6]; v3.y = a3[r][7];
                op[0] = v0; op[1] = v1; op[2] = v2; op[3] = v3;
            }
        }
    }
}

extern "C" void kernel_launch(void* const* d_in, const int* in_sizes, int n_in,
                              void* d_out, int out_size)
{
    const float* t   = (const float*)d_in[0];
    const float* emb = (const float*)d_in[1];
    const float* pa  = (const float*)d_in[3];
    const float* Wt1 = (const float*)d_in[9];
    const float* bt1 = (const float*)d_in[10];
    const float* Wt2 = (const float*)d_in[11];
    const float* bt2 = (const float*)d_in[12];
    const float* Wd1 = (const float*)d_in[13];
    const float* bd1 = (const float*)d_in[14];
    const float* Wd2 = (const float*)d_in[15];
    const float* bd2 = (const float*)d_in[16];
    const float* Wd3 = (const float*)d_in[17];
    const float* bd3 = (const float*)d_in[18];
    float* out = (float*)d_out;

    const int nrows = in_sizes[1] / HID;

    setup_kernel<<<1, 64>>>(t, pa, Wt1, bt1, Wt2, bt2, Wd1, bd1);
    mlp_kernel<<<(nrows + RPB - 1) / RPB, TPB>>>(emb, Wd1, Wd2, bd2, Wd3, bd3, out, nrows);
}